// round 16
// baseline (speedup 1.0000x reference)
#include <cuda_runtime.h>

#define T_FRAMES 60
#define HID 32
#define NG 128          // 4*HID gate values per frame
#define EPSF 1e-5f
#define FULLM 0xffffffffu

typedef unsigned long long ULL;

// per-frame gate pre-activations, PAIR-INTERLEAVED layout:
//   [t][e*2+0]=0.5*gi, [t][e*2+1]=0.5*gf, [t][64+e*2+0]=gg, [t][64+e*2+1]=0.5*go
__device__ float g_gx[T_FRAMES * NG];
__device__ int   g_done = 0;

__device__ __forceinline__ float tanha(float x) {
    float r; asm("tanh.approx.f32 %0, %1;" : "=f"(r) : "f"(x)); return r;
}
__device__ __forceinline__ ULL pack2(float lo, float hi) {
    ULL r; asm("mov.b64 %0, {%1, %2};" : "=l"(r) : "f"(lo), "f"(hi)); return r;
}
__device__ __forceinline__ void unpack2(ULL v, float& lo, float& hi) {
    asm("mov.b64 {%0, %1}, %2;" : "=f"(lo), "=f"(hi) : "l"(v));
}
__device__ __forceinline__ ULL ffma2(ULL a, ULL b, ULL c) {
    ULL d; asm("fma.rn.f32x2 %0, %1, %2, %3;" : "=l"(d) : "l"(a), "l"(b), "l"(c)); return d;
}
__device__ __forceinline__ ULL add2(ULL a, ULL b) {
    ULL d; asm("add.rn.f32x2 %0, %1, %2;" : "=l"(d) : "l"(a), "l"(b)); return d;
}

// ---------------------------------------------------------------------------
// Fused kernel: blocks 0..59 = per-frame MLP+LN+W_ih matvec (parallel),
// block 60 = recurrence (single warp, f32x2, NO block barrier) + head.
// ---------------------------------------------------------------------------
__global__ void __launch_bounds__(128, 1) fused_kernel(
    const float* __restrict__ x,
    const float* __restrict__ w00, const float* __restrict__ b00,
    const float* __restrict__ w01, const float* __restrict__ b01,
    const float* __restrict__ lng, const float* __restrict__ lnb,
    const float* __restrict__ wih, const float* __restrict__ bih,
    const float* __restrict__ bhh,
    const float* __restrict__ whh,
    const float* __restrict__ bng, const float* __restrict__ bnb,
    const float* __restrict__ w10, const float* __restrict__ b10,
    const float* __restrict__ w11, const float* __restrict__ b11,
    const float* __restrict__ w12, const float* __restrict__ b12,
    float* __restrict__ out)
{
    const int tid  = threadIdx.x;
    const int wid  = tid >> 5;
    const int lane = tid & 31;

    if (blockIdx.x < T_FRAMES) {
        // =================== frame path (parallel over t) ===================
        const int t = blockIdx.x;

        __shared__ float sx[64];
        __shared__ float sf1[64];
        __shared__ float sf2[64];
        __shared__ float sfn[64];
        __shared__ float s_mu, s_rstd;

        if (tid < 64) sx[tid] = (tid < 63) ? x[t * 63 + tid] : 0.0f;
        __syncthreads();

        // Layer 0: 63 rows, 2-way split-k
        {
            const int r    = tid >> 1;
            const int half = tid & 1;
            float acc = 0.0f;
            if (r < 63) {
                const float* wr = w00 + r * 63;
                if (half == 0) {
                    #pragma unroll
                    for (int k = 0; k < 32; k++) acc = fmaf(wr[k], sx[k], acc);
                } else {
                    #pragma unroll
                    for (int k = 32; k < 63; k++) acc = fmaf(wr[k], sx[k], acc);
                }
            }
            acc += __shfl_xor_sync(FULLM, acc, 1);
            if (r < 63 && half == 0) sf1[r] = fmaxf(acc + b00[r], 0.0f);
            if (tid == 126) sf1[63] = 0.0f;
        }
        __syncthreads();

        // Layer 1: 64 rows, 2-way split-k
        {
            const int r    = tid >> 1;
            const int half = tid & 1;
            const float* wr = w01 + r * 63;
            float acc = 0.0f;
            if (half == 0) {
                #pragma unroll
                for (int k = 0; k < 32; k++) acc = fmaf(wr[k], sf1[k], acc);
            } else {
                #pragma unroll
                for (int k = 32; k < 63; k++) acc = fmaf(wr[k], sf1[k], acc);
            }
            acc += __shfl_xor_sync(FULLM, acc, 1);
            if (half == 0) sf2[r] = fmaxf(acc + b01[r], 0.0f);
        }
        __syncthreads();

        if (tid < 32) {
            float v0 = sf2[tid], v1 = sf2[tid + 32];
            float s = v0 + v1;
            float q = v0 * v0 + v1 * v1;
            #pragma unroll
            for (int o = 16; o > 0; o >>= 1) {
                s += __shfl_xor_sync(FULLM, s, o);
                q += __shfl_xor_sync(FULLM, q, o);
            }
            if (tid == 0) {
                float mu  = s * (1.0f / 64.0f);
                float var = q * (1.0f / 64.0f) - mu * mu;
                s_mu   = mu;
                s_rstd = rsqrtf(var + EPSF);
            }
        }
        __syncthreads();

        if (tid < 64)
            sfn[tid] = (sf2[tid] - s_mu) * s_rstd * lng[tid] + lnb[tid];
        __syncthreads();

        {
            float acc = bih[tid] + bhh[tid];
            const float* wr = wih + tid * 64;
            #pragma unroll
            for (int k = 0; k < 64; k++) acc = fmaf(wr[k], sfn[k], acc);
            const int gr = tid >> 5;   // gate (0=i,1=f,2=g,3=o)
            const int el = tid & 31;   // element
            float scale = (gr == 2) ? 1.0f : 0.5f;   // sigmoid half-arg fold
            int slot = ((gr >= 2) ? 64 : 0) + el * 2 + (gr & 1);
            g_gx[t * NG + slot] = acc * scale;       // pair-interleaved
        }
        __syncthreads();
        if (tid == 0) {
            __threadfence();
            atomicAdd(&g_done, 1);
        }
        return;
    }

    // ======================= sequential path (block 60) =====================
    // Warp 0 runs the whole recurrence: lane e owns all 4 gate rows of
    // element e (weights packed as f32x2 pairs). h is broadcast through a
    // DUPLICATED smem buffer so one LDS.128 yields two (h,h) f32x2 operands.
    // NO block barrier in the loop — only one __syncwarp per step.
    __shared__ float sgx[T_FRAMES * NG];              // 30 KB staged gx
    __shared__ __align__(16) float shd[2][2 * HID];   // duplicated h (=2h), 2 bufs
    __shared__ volatile float s_sink;

    // weights -> registers in warp 0 only (overlaps the frame phase).
    // wif2[k] = (wi*0.25, wf*0.25); wgo2[k] = (wg*0.5, wo*0.25)
    // (x0.5 sigmoid half-arg for i/f/o; x0.5 everywhere for hp = 2h operand)
    ULL wif2[HID], wgo2[HID];
    if (wid == 0) {
        const float* ri = whh + (lane      ) * HID;
        const float* rf = whh + (lane + 32 ) * HID;
        const float* rg = whh + (lane + 64 ) * HID;
        const float* ro = whh + (lane + 96 ) * HID;
        #pragma unroll
        for (int k = 0; k < HID; k++) {
            wif2[k] = pack2(ri[k] * 0.25f, rf[k] * 0.25f);
            wgo2[k] = pack2(rg[k] * 0.5f,  ro[k] * 0.25f);
        }
    }

    // head-weight L1 warm (off critical path, during frame phase)
    {
        float acc = 0.0f;
        #pragma unroll 4
        for (int i = tid * 8; i < 256 * 32; i += 128 * 8) acc += w12[i];
        for (int i = tid * 8; i < 32 * 32; i += 128 * 8) acc += w10[i] + w11[i];
        if (tid < 32) acc += b10[tid] + b11[tid] + bng[tid] + bnb[tid];
        if (tid < 64) acc += b12[tid * 4];
        s_sink = acc;
    }

    // wait for all frame blocks
    if (tid == 0) {
        volatile int* p = &g_done;
        while (*p < T_FRAMES) { }
        __threadfence();
    }
    __syncthreads();

    // bulk-stage gx into smem (all 4 warps)
    {
        float4* s4 = reinterpret_cast<float4*>(sgx);
        const float4* g4 = reinterpret_cast<const float4*>(g_gx);
        #pragma unroll
        for (int i = tid; i < (T_FRAMES * NG) / 4; i += 128)
            s4[i] = __ldcg(g4 + i);
    }
    __syncthreads();

    // ------------------- recurrence: WARP 0 ONLY -------------------
    if (wid == 0) {
        float c;

        // ---- t = 0 peeled: h = 0 -> gates are just gx[0] ----
        {
            float gi, gf, gg, go;
            unpack2(*reinterpret_cast<const ULL*>(&sgx[2 * lane]), gi, gf);
            unpack2(*reinterpret_cast<const ULL*>(&sgx[64 + 2 * lane]), gg, go);
            (void)gf;
            float ti = tanha(gi);
            float tg = tanha(gg);
            float to = tanha(go);
            c = 0.5f * fmaf(ti, tg, tg);          // sigma_i*tanh_g (c0 = 0)
            float th = tanha(c);
            float hp = fmaf(to, th, th);          // 2h
            *reinterpret_cast<ULL*>(&shd[1][2 * lane]) = pack2(hp, hp);
            __syncwarp();
        }

        #pragma unroll 1
        for (int t = 1; t < T_FRAMES; t++) {
            const ulonglong2* hb =
                reinterpret_cast<const ulonglong2*>(shd[t & 1]);
            ULL aif[4], ago[4];
            aif[0] = *reinterpret_cast<const ULL*>(&sgx[t * NG + 2 * lane]);
            ago[0] = *reinterpret_cast<const ULL*>(&sgx[t * NG + 64 + 2 * lane]);
            #pragma unroll
            for (int i = 1; i < 4; i++) { aif[i] = 0ull; ago[i] = 0ull; }

            #pragma unroll
            for (int kk = 0; kk < 16; kk++) {     // 2 k-values per LDS.128
                ulonglong2 hv = hb[kk];           // (h2k,h2k) , (h2k+1,h2k+1)
                const int j = kk & 3;
                aif[j] = ffma2(wif2[2 * kk    ], hv.x, aif[j]);
                aif[j] = ffma2(wif2[2 * kk + 1], hv.y, aif[j]);
                ago[j] = ffma2(wgo2[2 * kk    ], hv.x, ago[j]);
                ago[j] = ffma2(wgo2[2 * kk + 1], hv.y, ago[j]);
            }
            float gi, gf, gg, go;
            unpack2(add2(add2(aif[0], aif[1]), add2(aif[2], aif[3])), gi, gf);
            unpack2(add2(add2(ago[0], ago[1]), add2(ago[2], ago[3])), gg, go);

            float ti = tanha(gi);
            float tf = tanha(gf);
            float tg = tanha(gg);
            float to = tanha(go);
            // c = sigma_f*c + sigma_i*tanh_g = 0.5*((tf*c+c) + (ti*tg+tg))
            c = 0.5f * (fmaf(tf, c, c) + fmaf(ti, tg, tg));
            float th = tanha(c);
            float hp = fmaf(to, th, th);          // 2h

            *reinterpret_cast<ULL*>(&shd[(t + 1) & 1][2 * lane]) = pack2(hp, hp);
            __syncwarp();                         // only sync in the loop
        }
    }
    __syncthreads();     // warps 1..3 wait here; h now published in shd[0]

    // ---- output head (all 4 warps) ----
    float h  = 0.5f * shd[T_FRAMES & 1][2 * lane];   // t=59 wrote shd[0]
    float hb = (h * rsqrtf(1.0f + EPSF)) * bng[lane] + bnb[lane];

    float o1 = b10[lane];
    #pragma unroll
    for (int k = 0; k < 32; k++)
        o1 = fmaf(w10[lane * 32 + k], __shfl_sync(FULLM, hb, k), o1);
    o1 = fmaxf(o1, 0.0f);

    float o2 = b11[lane];
    #pragma unroll
    for (int k = 0; k < 32; k++)
        o2 = fmaf(w11[lane * 32 + k], __shfl_sync(FULLM, o1, k), o2);
    o2 = fmaxf(o2, 0.0f);

    // warp w -> output rows [64w, 64w+64): 2 rows per lane
    const int r0 = wid * 64 + lane;
    const int r1 = r0 + 32;
    float a0 = b12[r0], a1 = b12[r1];
    #pragma unroll
    for (int k = 0; k < 32; k++) {
        float v = __shfl_sync(FULLM, o2, k);
        a0 = fmaf(w12[r0 * 32 + k], v, a0);
        a1 = fmaf(w12[r1 * 32 + k], v, a1);
    }
    out[r0] = a0;
    out[r1] = a1;

    // reset counter for next replay
    __syncthreads();
    if (tid == 0) g_done = 0;
}

// ---------------------------------------------------------------------------
// Input order (metadata): x, w00, b00, w01, b01, ln_g, ln_b, w_ih, w_hh,
//                         b_ih, b_hh, bn_g, bn_b, w10, b10, w11, b11, w12, b12
// ---------------------------------------------------------------------------
extern "C" void kernel_launch(void* const* d_in, const int* in_sizes, int n_in,
                              void* d_out, int out_size)
{
    const float* x    = (const float*)d_in[0];
    const float* w00  = (const float*)d_in[1];
    const float* b00  = (const float*)d_in[2];
    const float* w01  = (const float*)d_in[3];
    const float* b01  = (const float*)d_in[4];
    const float* lng  = (const float*)d_in[5];
    const float* lnb  = (const float*)d_in[6];
    const float* wih  = (const float*)d_in[7];
    const float* whh  = (const float*)d_in[8];
    const float* bih  = (const float*)d_in[9];
    const float* bhh  = (const float*)d_in[10];
    const float* bng  = (const float*)d_in[11];
    const float* bnb  = (const float*)d_in[12];
    const float* w10  = (const float*)d_in[13];
    const float* b10  = (const float*)d_in[14];
    const float* w11  = (const float*)d_in[15];
    const float* b11  = (const float*)d_in[16];
    const float* w12  = (const float*)d_in[17];
    const float* b12  = (const float*)d_in[18];
    float* out = (float*)d_out;

    fused_kernel<<<T_FRAMES + 1, 128>>>(
        x, w00, b00, w01, b01, lng, lnb, wih, bih, bhh,
        whh, bng, bnb, w10, b10, w11, b11, w12, b12, out);
}